// round 9
// baseline (speedup 1.0000x reference)
#include <cuda_runtime.h>

// out[32, N] = scatter-add of sparse COO (rows, cols, values) on x[64, N].
// R3-R6: kernel pinned at 20.2-20.5us, every resource ~50% => composite /
// wave-quantization limited (grid 7840 = ~9 waves @ 6 blocks/SM, bimodal
// block durations -> straggler tails each wave). R7: single-wave persistent
// blocks (grid ~= 148*6), grid-stride over chunks, term-match hoisted; pure
// zero-store fast path for the 29/32 empty rows.

#define OUTF 32
#define UNROLL 4
#define MAX_NNZ 64
#define MAX_TERMS 8
#define BLOCK 256
#define BLOCKS_X 28   // 28*32 = 896 blocks ~= 148 SMs * 6 blocks

__global__ void spmm_persistent_kernel(const float4* __restrict__ x,      // [64, n4]
                                       const float*  __restrict__ values, // [nnz]
                                       const int*    __restrict__ rows,   // [nnz]
                                       const int*    __restrict__ cols,   // [nnz]
                                       float4*       __restrict__ out,    // [32, n4]
                                       int n4, int nnz, int nchunks)
{
    __shared__ float s_val[MAX_NNZ];
    __shared__ int   s_row[MAX_NNZ];
    __shared__ int   s_col[MAX_NNZ];

    if (threadIdx.x < nnz) {
        s_val[threadIdx.x] = values[threadIdx.x];
        s_row[threadIdx.x] = rows[threadIdx.x];
        s_col[threadIdx.x] = cols[threadIdx.x];
    }
    __syncthreads();

    const int r = blockIdx.y;
    float4* __restrict__ orow = out + (long)r * n4;

    // Hoist term matching (uniform per block).
    int nmatch = 0;
    float mv[MAX_TERMS];
    const float4* mx[MAX_TERMS];
    for (int t = 0; t < nnz; t++) {
        if (s_row[t] == r && nmatch < MAX_TERMS) {
            mv[nmatch] = s_val[t];
            mx[nmatch] = x + (long)s_col[t] * n4;
            nmatch++;
        }
    }

    const int chunk_elems = BLOCK * UNROLL;  // float4s per chunk

    if (nmatch == 0) {
        // Pure zero-store path: no accumulator dependencies, stores free-run.
        const float4 z = make_float4(0.f, 0.f, 0.f, 0.f);
        for (int c = blockIdx.x; c < nchunks; c += BLOCKS_X) {
            const long base = (long)c * chunk_elems + threadIdx.x;
            #pragma unroll
            for (int k = 0; k < UNROLL; k++) {
                const long j = base + (long)k * BLOCK;
                if (j < n4) orow[j] = z;
            }
        }
        return;
    }

    for (int c = blockIdx.x; c < nchunks; c += BLOCKS_X) {
        const long base = (long)c * chunk_elems + threadIdx.x;

        float4 acc[UNROLL];
        #pragma unroll
        for (int k = 0; k < UNROLL; k++)
            acc[k] = make_float4(0.f, 0.f, 0.f, 0.f);

        for (int t = 0; t < nmatch; t++) {
            const float v = mv[t];
            const float4* __restrict__ xr = mx[t];
            #pragma unroll
            for (int k = 0; k < UNROLL; k++) {
                const long j = base + (long)k * BLOCK;
                if (j < n4) {
                    const float4 xv = xr[j];
                    acc[k].x = fmaf(v, xv.x, acc[k].x);
                    acc[k].y = fmaf(v, xv.y, acc[k].y);
                    acc[k].z = fmaf(v, xv.z, acc[k].z);
                    acc[k].w = fmaf(v, xv.w, acc[k].w);
                }
            }
        }

        #pragma unroll
        for (int k = 0; k < UNROLL; k++) {
            const long j = base + (long)k * BLOCK;
            if (j < n4) orow[j] = acc[k];
        }
    }
}

// Scalar tail for N % 4 != 0 (not hit for N=1e6).
__global__ void spmm_tail_kernel(const float* __restrict__ x,
                                 const float* __restrict__ values,
                                 const int*   __restrict__ rows,
                                 const int*   __restrict__ cols,
                                 float* __restrict__ out,
                                 int N, int tail_start, int nnz)
{
    const int r = blockIdx.y;
    const int j = tail_start + blockIdx.x * blockDim.x + threadIdx.x;
    if (j >= N) return;
    float acc = 0.f;
    for (int t = 0; t < nnz; t++)
        if (rows[t] == r)
            acc = fmaf(values[t], x[(long)cols[t] * N + j], acc);
    out[(long)r * N + j] = acc;
}

extern "C" void kernel_launch(void* const* d_in, const int* in_sizes, int n_in,
                              void* d_out, int out_size)
{
    const float* x      = (const float*)d_in[0];  // [64, N]
    const float* values = (const float*)d_in[1];  // [nnz]
    const int*   rows   = (const int*)d_in[2];    // [nnz]
    const int*   cols   = (const int*)d_in[3];    // [nnz]
    float* out = (float*)d_out;                   // [32, N]

    int nnz = in_sizes[1];
    if (nnz > MAX_NNZ) nnz = MAX_NNZ;             // contract: tiny sparse pattern
    const int N  = out_size / OUTF;               // 1,000,000
    const int n4 = N / 4;

    if (n4 > 0) {
        const int chunk_elems = BLOCK * UNROLL;
        const int nchunks = (n4 + chunk_elems - 1) / chunk_elems;  // 245
        dim3 grid(BLOCKS_X, OUTF);                // 896 blocks ~ one wave
        spmm_persistent_kernel<<<grid, BLOCK>>>(
            (const float4*)x, values, rows, cols, (float4*)out,
            n4, nnz, nchunks);
    }

    const int tail_start = n4 * 4;
    if (tail_start < N) {
        const int tail = N - tail_start;
        dim3 grid((tail + 127) / 128, OUTF);
        spmm_tail_kernel<<<grid, 128>>>(x, values, rows, cols, out,
                                        N, tail_start, nnz);
    }
}

// round 11
// speedup vs baseline: 1.0526x; 1.0526x over previous
#include <cuda_runtime.h>

// out[32, N] = scatter-add of sparse COO (rows, cols, values) on x[64, N].
// R9 post-mortem: heterogeneous block costs (3 heavy rows vs 29 store-only
// rows) caused straggler tails however scheduled. R10: transpose the grid —
// 1D over column chunks, each block computes ALL 32 rows for its columns.
// Every block is identical: 3 x-loads + 32 row-stores per thread. Thread 0
// builds a per-row term CSR in shared once per block.

#define OUTF 32
#define MAX_NNZ 64
#define TPR 8           // max terms per row
#define BLOCK 256

__global__ void spmm_colmajor_kernel(const float4* __restrict__ x,      // [64, n4]
                                     const float*  __restrict__ values, // [nnz]
                                     const int*    __restrict__ rows,   // [nnz]
                                     const int*    __restrict__ cols,   // [nnz]
                                     float4*       __restrict__ out,    // [32, n4]
                                     int n4, int nnz)
{
    __shared__ int   s_nt[OUTF];
    __shared__ float s_v[OUTF][TPR];
    __shared__ long  s_off[OUTF][TPR];   // col * n4 (float4 element offset)

    if (threadIdx.x == 0) {
        #pragma unroll
        for (int r = 0; r < OUTF; r++) s_nt[r] = 0;
        for (int t = 0; t < nnz; t++) {
            const int r = rows[t];
            if ((unsigned)r < OUTF) {
                const int c = s_nt[r];
                if (c < TPR) {
                    s_v[r][c]   = values[t];
                    s_off[r][c] = (long)cols[t] * n4;
                    s_nt[r] = c + 1;
                }
            }
        }
    }
    __syncthreads();

    const long j = (long)blockIdx.x * BLOCK + threadIdx.x;
    if (j >= n4) return;

    float4* __restrict__ op = out + j;     // row 0, column j; stride n4 per row

    #pragma unroll 4
    for (int r = 0; r < OUTF; r++) {
        float4 acc = make_float4(0.f, 0.f, 0.f, 0.f);
        const int nt = s_nt[r];            // uniform -> LDS broadcast
        for (int t = 0; t < nt; t++) {
            const float  v  = s_v[r][t];
            const float4 xv = x[s_off[r][t] + j];
            acc.x = fmaf(v, xv.x, acc.x);
            acc.y = fmaf(v, xv.y, acc.y);
            acc.z = fmaf(v, xv.z, acc.z);
            acc.w = fmaf(v, xv.w, acc.w);
        }
        op[(long)r * n4] = acc;
    }
}

// Scalar tail for N % 4 != 0 (not hit for N=1e6).
__global__ void spmm_tail_kernel(const float* __restrict__ x,
                                 const float* __restrict__ values,
                                 const int*   __restrict__ rows,
                                 const int*   __restrict__ cols,
                                 float* __restrict__ out,
                                 int N, int tail_start, int nnz)
{
    const int r = blockIdx.y;
    const int j = tail_start + blockIdx.x * blockDim.x + threadIdx.x;
    if (j >= N) return;
    float acc = 0.f;
    for (int t = 0; t < nnz; t++)
        if (rows[t] == r)
            acc = fmaf(values[t], x[(long)cols[t] * N + j], acc);
    out[(long)r * N + j] = acc;
}

extern "C" void kernel_launch(void* const* d_in, const int* in_sizes, int n_in,
                              void* d_out, int out_size)
{
    const float* x      = (const float*)d_in[0];  // [64, N]
    const float* values = (const float*)d_in[1];  // [nnz]
    const int*   rows   = (const int*)d_in[2];    // [nnz]
    const int*   cols   = (const int*)d_in[3];    // [nnz]
    float* out = (float*)d_out;                   // [32, N]

    int nnz = in_sizes[1];
    if (nnz > MAX_NNZ) nnz = MAX_NNZ;             // contract: tiny sparse pattern
    const int N  = out_size / OUTF;               // 1,000,000
    const int n4 = N / 4;

    if (n4 > 0) {
        const int grid = (n4 + BLOCK - 1) / BLOCK;   // 977 uniform blocks
        spmm_colmajor_kernel<<<grid, BLOCK>>>(
            (const float4*)x, values, rows, cols, (float4*)out, n4, nnz);
    }

    const int tail_start = n4 * 4;
    if (tail_start < N) {
        const int tail = N - tail_start;
        dim3 grid((tail + 127) / 128, OUTF);
        spmm_tail_kernel<<<grid, 128>>>(x, values, rows, cols, out,
                                        N, tail_start, nnz);
    }
}

// round 12
// speedup vs baseline: 1.3187x; 1.2527x over previous
#include <cuda_runtime.h>

// out[32, N] = scatter-add of sparse COO (rows, cols, values) on x[64, N].
// Converged architecture (R3 shape proven best over R4-R11 alternatives):
// grid (chunks, 32 rows), 64B/thread, shared-staged COO, __stcs stores.
// R12: block 128 instead of 256 -> 2x finer scheduling quanta (15648 blocks)
// to pack wave tails; body unchanged.

#define OUTF 32
#define UNROLL 4
#define MAX_NNZ 64
#define BLOCK 128

__global__ void spmm_fused_kernel(const float4* __restrict__ x,      // [64, n4]
                                  const float*  __restrict__ values, // [nnz]
                                  const int*    __restrict__ rows,   // [nnz]
                                  const int*    __restrict__ cols,   // [nnz]
                                  float4*       __restrict__ out,    // [32, n4]
                                  int n4, int nnz)
{
    __shared__ float s_val[MAX_NNZ];
    __shared__ int   s_row[MAX_NNZ];
    __shared__ int   s_col[MAX_NNZ];

    if (threadIdx.x < nnz) {
        s_val[threadIdx.x] = values[threadIdx.x];
        s_row[threadIdx.x] = rows[threadIdx.x];
        s_col[threadIdx.x] = cols[threadIdx.x];
    }
    __syncthreads();

    const int r = blockIdx.y;
    const long base = (long)blockIdx.x * (BLOCK * UNROLL) + threadIdx.x;

    float4 acc[UNROLL];
    #pragma unroll
    for (int k = 0; k < UNROLL; k++)
        acc[k] = make_float4(0.f, 0.f, 0.f, 0.f);

    for (int t = 0; t < nnz; t++) {
        if (s_row[t] == r) {                 // uniform across block
            const float v = s_val[t];
            const float4* __restrict__ xr = x + (long)s_col[t] * n4;
            #pragma unroll
            for (int k = 0; k < UNROLL; k++) {
                const long j = base + (long)k * BLOCK;
                if (j < n4) {
                    const float4 xv = xr[j];
                    acc[k].x = fmaf(v, xv.x, acc[k].x);
                    acc[k].y = fmaf(v, xv.y, acc[k].y);
                    acc[k].z = fmaf(v, xv.z, acc[k].z);
                    acc[k].w = fmaf(v, xv.w, acc[k].w);
                }
            }
        }
    }

    float4* __restrict__ orow = out + (long)r * n4;
    #pragma unroll
    for (int k = 0; k < UNROLL; k++) {
        const long j = base + (long)k * BLOCK;
        if (j < n4) __stcs(&orow[j], acc[k]);   // evict-first: never re-read
    }
}

// Scalar tail for N % 4 != 0 (not hit for N=1e6).
__global__ void spmm_tail_kernel(const float* __restrict__ x,
                                 const float* __restrict__ values,
                                 const int*   __restrict__ rows,
                                 const int*   __restrict__ cols,
                                 float* __restrict__ out,
                                 int N, int tail_start, int nnz)
{
    const int r = blockIdx.y;
    const int j = tail_start + blockIdx.x * blockDim.x + threadIdx.x;
    if (j >= N) return;
    float acc = 0.f;
    for (int t = 0; t < nnz; t++)
        if (rows[t] == r)
            acc = fmaf(values[t], x[(long)cols[t] * N + j], acc);
    out[(long)r * N + j] = acc;
}

extern "C" void kernel_launch(void* const* d_in, const int* in_sizes, int n_in,
                              void* d_out, int out_size)
{
    const float* x      = (const float*)d_in[0];  // [64, N]
    const float* values = (const float*)d_in[1];  // [nnz]
    const int*   rows   = (const int*)d_in[2];    // [nnz]
    const int*   cols   = (const int*)d_in[3];    // [nnz]
    float* out = (float*)d_out;                   // [32, N]

    int nnz = in_sizes[1];
    if (nnz > MAX_NNZ) nnz = MAX_NNZ;             // contract: tiny sparse pattern
    const int N  = out_size / OUTF;               // 1,000,000
    const int n4 = N / 4;

    if (n4 > 0) {
        const int per_block = BLOCK * UNROLL;     // float4s per block
        dim3 grid((n4 + per_block - 1) / per_block, OUTF);
        spmm_fused_kernel<<<grid, BLOCK>>>(
            (const float4*)x, values, rows, cols, (float4*)out, n4, nnz);
    }

    const int tail_start = n4 * 4;
    if (tail_start < N) {
        const int tail = N - tail_start;
        dim3 grid((tail + 127) / 128, OUTF);
        spmm_tail_kernel<<<grid, 128>>>(x, values, rows, cols, out,
                                        N, tail_start, nnz);
    }
}

// round 14
// speedup vs baseline: 1.3352x; 1.0125x over previous
#include <cuda_runtime.h>

// out[32, N] = scatter-add of sparse COO (rows, cols, values) on x[64, N].
// Converged R3-family shape: grid (chunks, 32 rows), shared-staged COO,
// uniform per-block row match, __stcs streaming stores.
// R13: UNROLL=2 (32B/thread) to cut regs -> occupancy cap 48->64 warps/SM,
// +33% bytes-in-flight (the occupancy-side counterpart of R4's failed
// ILP-side attempt; R4 failed via spills, this cannot spill).

#define OUTF 32
#define UNROLL 2
#define MAX_NNZ 64
#define BLOCK 256

__global__ void spmm_fused_kernel(const float4* __restrict__ x,      // [64, n4]
                                  const float*  __restrict__ values, // [nnz]
                                  const int*    __restrict__ rows,   // [nnz]
                                  const int*    __restrict__ cols,   // [nnz]
                                  float4*       __restrict__ out,    // [32, n4]
                                  int n4, int nnz)
{
    __shared__ float s_val[MAX_NNZ];
    __shared__ int   s_row[MAX_NNZ];
    __shared__ int   s_col[MAX_NNZ];

    if (threadIdx.x < nnz) {
        s_val[threadIdx.x] = values[threadIdx.x];
        s_row[threadIdx.x] = rows[threadIdx.x];
        s_col[threadIdx.x] = cols[threadIdx.x];
    }
    __syncthreads();

    const int r = blockIdx.y;
    const long base = (long)blockIdx.x * (BLOCK * UNROLL) + threadIdx.x;

    float4 acc[UNROLL];
    #pragma unroll
    for (int k = 0; k < UNROLL; k++)
        acc[k] = make_float4(0.f, 0.f, 0.f, 0.f);

    for (int t = 0; t < nnz; t++) {
        if (s_row[t] == r) {                 // uniform across block
            const float v = s_val[t];
            const float4* __restrict__ xr = x + (long)s_col[t] * n4;
            #pragma unroll
            for (int k = 0; k < UNROLL; k++) {
                const long j = base + (long)k * BLOCK;
                if (j < n4) {
                    const float4 xv = xr[j];
                    acc[k].x = fmaf(v, xv.x, acc[k].x);
                    acc[k].y = fmaf(v, xv.y, acc[k].y);
                    acc[k].z = fmaf(v, xv.z, acc[k].z);
                    acc[k].w = fmaf(v, xv.w, acc[k].w);
                }
            }
        }
    }

    float4* __restrict__ orow = out + (long)r * n4;
    #pragma unroll
    for (int k = 0; k < UNROLL; k++) {
        const long j = base + (long)k * BLOCK;
        if (j < n4) __stcs(&orow[j], acc[k]);   // evict-first: never re-read
    }
}

// Scalar tail for N % 4 != 0 (not hit for N=1e6).
__global__ void spmm_tail_kernel(const float* __restrict__ x,
                                 const float* __restrict__ values,
                                 const int*   __restrict__ rows,
                                 const int*   __restrict__ cols,
                                 float* __restrict__ out,
                                 int N, int tail_start, int nnz)
{
    const int r = blockIdx.y;
    const int j = tail_start + blockIdx.x * blockDim.x + threadIdx.x;
    if (j >= N) return;
    float acc = 0.f;
    for (int t = 0; t < nnz; t++)
        if (rows[t] == r)
            acc = fmaf(values[t], x[(long)cols[t] * N + j], acc);
    out[(long)r * N + j] = acc;
}

extern "C" void kernel_launch(void* const* d_in, const int* in_sizes, int n_in,
                              void* d_out, int out_size)
{
    const float* x      = (const float*)d_in[0];  // [64, N]
    const float* values = (const float*)d_in[1];  // [nnz]
    const int*   rows   = (const int*)d_in[2];    // [nnz]
    const int*   cols   = (const int*)d_in[3];    // [nnz]
    float* out = (float*)d_out;                   // [32, N]

    int nnz = in_sizes[1];
    if (nnz > MAX_NNZ) nnz = MAX_NNZ;             // contract: tiny sparse pattern
    const int N  = out_size / OUTF;               // 1,000,000
    const int n4 = N / 4;

    if (n4 > 0) {
        const int per_block = BLOCK * UNROLL;     // float4s per block
        dim3 grid((n4 + per_block - 1) / per_block, OUTF);
        spmm_fused_kernel<<<grid, BLOCK>>>(
            (const float4*)x, values, rows, cols, (float4*)out, n4, nnz);
    }

    const int tail_start = n4 * 4;
    if (tail_start < N) {
        const int tail = N - tail_start;
        dim3 grid((tail + 127) / 128, OUTF);
        spmm_tail_kernel<<<grid, 128>>>(x, values, rows, cols, out,
                                        N, tail_start, nnz);
    }
}